// round 1
// baseline (speedup 1.0000x reference)
#include <cuda_runtime.h>
#include <cstdint>

// Problem constants
#define IM_PIX   16384      // 128*128 pixels
#define BC       32         // 2*16 maps
#define HT_BINS  33120      // 184*180
#define N_VOTES  4000000
#define INV_NORM (1.0f/128.0f)

// Scratch (allocation-free rule: __device__ globals)
__device__ float g_xT[IM_PIX * BC];    // pixel-major x transpose, 2 MB
__device__ float g_acc[HT_BINS * BC];  // bin-major accumulator, 4.24 MB

// ---------------------------------------------------------------------------
// Zero the accumulator (d_out is poisoned; acc must start at 0 every call)
// ---------------------------------------------------------------------------
__global__ void zero_acc_kernel() {
    int i = blockIdx.x * blockDim.x + threadIdx.x;
    if (i < HT_BINS * BC) g_acc[i] = 0.0f;
}

// ---------------------------------------------------------------------------
// Transpose x [BC, IM_PIX] (map-major) -> g_xT [IM_PIX, BC] (pixel-major)
// so each vote's 32-map gather is one contiguous 128B row.
// ---------------------------------------------------------------------------
__global__ void transpose_x_kernel(const float* __restrict__ x) {
    int i = blockIdx.x * blockDim.x + threadIdx.x;
    if (i < IM_PIX * BC) {
        int m = i >> 14;          // i / 16384
        int p = i & (IM_PIX - 1); // i % 16384
        g_xT[p * BC + m] = x[i];
    }
}

// ---------------------------------------------------------------------------
// Main vote kernel: 8 lanes cooperate on one vote.
//   lane sub-id s in [0,8): handles maps [4s, 4s+4) via float4.
// Gather:  one coalesced 128B row from g_xT[pixel]
// Scatter: red.global.add.v4.f32 into one 128B row of g_acc[bin]
// ---------------------------------------------------------------------------
__global__ void vote_kernel(const int*   __restrict__ vote_pixel,
                            const int*   __restrict__ vote_bin,
                            const float* __restrict__ vote_weight) {
    long long t = (long long)blockIdx.x * blockDim.x + threadIdx.x;
    int v   = (int)(t >> 3);
    int sub = (int)(t & 7);
    if (v >= N_VOTES) return;

    // All 8 lanes of a group read the same addresses -> L1 sector broadcast
    int   p = vote_pixel[v];
    int   b = vote_bin[v];
    float w = vote_weight[v];

    const float4* src = reinterpret_cast<const float4*>(g_xT + (size_t)p * BC) + sub;
    float4 xv = __ldg(src);

    float4 r;
    r.x = xv.x * w;
    r.y = xv.y * w;
    r.z = xv.z * w;
    r.w = xv.w * w;

    float* dst = g_acc + (size_t)b * BC + sub * 4;
    asm volatile("red.global.add.v4.f32 [%0], {%1, %2, %3, %4};"
                 :: "l"(dst), "f"(r.x), "f"(r.y), "f"(r.z), "f"(r.w)
                 : "memory");
}

// ---------------------------------------------------------------------------
// Finalize: acc [HT_BINS, BC] bin-major -> out [BC, HT_BINS] map-major, /NORM
// Reads fully coalesced; writes strided (only 4.2 MB, negligible).
// ---------------------------------------------------------------------------
__global__ void finalize_kernel(float* __restrict__ out) {
    int i = blockIdx.x * blockDim.x + threadIdx.x;  // i = b*32 + m
    if (i < HT_BINS * BC) {
        int b = i >> 5;
        int m = i & 31;
        out[(size_t)m * HT_BINS + b] = g_acc[i] * INV_NORM;
    }
}

// ---------------------------------------------------------------------------
// Launch: zero -> transpose -> votes -> finalize (all async, graph-capturable)
// ---------------------------------------------------------------------------
extern "C" void kernel_launch(void* const* d_in, const int* in_sizes, int n_in,
                              void* d_out, int out_size) {
    const float* x  = (const float*)d_in[0];   // [2,16,128,128] fp32
    const int*   vp = (const int*)  d_in[1];   // vote_pixel  [4M] int32
    const int*   vb = (const int*)  d_in[2];   // vote_bin    [4M] int32
    const float* vw = (const float*)d_in[3];   // vote_weight [4M] fp32
    float* out = (float*)d_out;                // [2,16,184,180] fp32

    const int TB = 256;

    zero_acc_kernel   <<<(HT_BINS * BC + TB - 1) / TB, TB>>>();
    transpose_x_kernel<<<(IM_PIX * BC + TB - 1) / TB, TB>>>(x);

    long long work = (long long)N_VOTES * 8;
    int grid = (int)((work + TB - 1) / TB);
    vote_kernel<<<grid, TB>>>(vp, vb, vw);

    finalize_kernel<<<(HT_BINS * BC + TB - 1) / TB, TB>>>(out);
}

// round 2
// speedup vs baseline: 1.1022x; 1.1022x over previous
#include <cuda_runtime.h>
#include <cuda_fp16.h>
#include <cstdint>

// Problem constants
#define IM_PIX   16384      // 128*128 pixels
#define BC       32         // 2*16 maps
#define HT_BINS  33120      // 184*180
#define N_VOTES  4000000
#define INV_NORM (1.0f/128.0f)

// Scratch (allocation-free rule: __device__ globals)
__device__ __half g_xTh[IM_PIX * BC];   // pixel-major x transpose, fp16, 1 MB
__device__ float  g_acc[HT_BINS * BC];  // bin-major accumulator, fp32, 4.24 MB

// ---------------------------------------------------------------------------
// Zero the accumulator, vectorized. HT_BINS*BC = 1,059,840 floats = 264,960 f4
// ---------------------------------------------------------------------------
__global__ void zero_acc_kernel() {
    int i = blockIdx.x * blockDim.x + threadIdx.x;
    if (i < (HT_BINS * BC) / 4)
        reinterpret_cast<float4*>(g_acc)[i] = make_float4(0.f, 0.f, 0.f, 0.f);
}

// ---------------------------------------------------------------------------
// Transpose x [BC, IM_PIX] fp32 -> g_xTh [IM_PIX, BC] fp16, tiled via smem.
// Block = 256 threads handles a tile of 64 pixels x 32 maps.
//   Load:  x[m][p0+pl]  -- coalesced over pl (64 consecutive floats per map)
//   Store: xTh[p][m]    -- 32 halves (64B) contiguous per pixel
// ---------------------------------------------------------------------------
__global__ void transpose_x_kernel(const float* __restrict__ x) {
    __shared__ float tile[32][64 + 1];   // [map][pixel_local], padded
    int p0 = blockIdx.x * 64;
    int t  = threadIdx.x;

    // load: 32 maps * 64 pixels = 2048 elems, 8 iters of 256
    #pragma unroll
    for (int i = 0; i < 8; i++) {
        int idx = t + i * 256;          // idx = m*64 + pl
        int m  = idx >> 6;
        int pl = idx & 63;
        tile[m][pl] = x[(size_t)m * IM_PIX + p0 + pl];
    }
    __syncthreads();

    // store: thread handles (pl, m); consecutive t -> consecutive m for fixed pl
    #pragma unroll
    for (int i = 0; i < 8; i++) {
        int idx = t + i * 256;          // idx = pl*32 + m
        int pl = idx >> 5;
        int m  = idx & 31;
        g_xTh[(size_t)(p0 + pl) * BC + m] = __float2half(tile[m][pl]);
    }
}

// ---------------------------------------------------------------------------
// Main vote kernel: 8 lanes cooperate on one vote.
//   lane sub in [0,8): maps [4*sub, 4*sub+4)
// Gather:  8B (4 x fp16) per lane -> one coalesced 64B row per vote
// Scatter: red.global.add.v4.f32 -> one 128B row of g_acc[bin]
// ---------------------------------------------------------------------------
__global__ void vote_kernel(const int*   __restrict__ vote_pixel,
                            const int*   __restrict__ vote_bin,
                            const float* __restrict__ vote_weight) {
    long long t = (long long)blockIdx.x * blockDim.x + threadIdx.x;
    int v   = (int)(t >> 3);
    int sub = (int)(t & 7);
    if (v >= N_VOTES) return;

    int   p = vote_pixel[v];
    int   b = vote_bin[v];
    float w = vote_weight[v];

    // 8-byte gather: 4 halves
    uint2 u = *reinterpret_cast<const uint2*>(g_xTh + (size_t)p * BC + sub * 4);
    __half2 h0 = *reinterpret_cast<__half2*>(&u.x);
    __half2 h1 = *reinterpret_cast<__half2*>(&u.y);
    float2 f0 = __half22float2(h0);
    float2 f1 = __half22float2(h1);

    float r0 = f0.x * w, r1 = f0.y * w, r2 = f1.x * w, r3 = f1.y * w;

    float* dst = g_acc + (size_t)b * BC + sub * 4;
    asm volatile("red.global.add.v4.f32 [%0], {%1, %2, %3, %4};"
                 :: "l"(dst), "f"(r0), "f"(r1), "f"(r2), "f"(r3)
                 : "memory");
}

// ---------------------------------------------------------------------------
// Finalize: acc [HT_BINS, BC] bin-major -> out [BC, HT_BINS] map-major, /NORM
// Tiled transpose: block handles 64 bins x 32 maps; both sides coalesced.
// ---------------------------------------------------------------------------
__global__ void finalize_kernel(float* __restrict__ out) {
    __shared__ float tile[64][32 + 1];   // [bin_local][map], padded
    int b0 = blockIdx.x * 64;
    int t  = threadIdx.x;

    // load: 64 bins * 32 maps, coalesced over map (128B per bin row)
    #pragma unroll
    for (int i = 0; i < 8; i++) {
        int idx = t + i * 256;          // idx = bl*32 + m
        int bl = idx >> 5;
        int m  = idx & 31;
        int b  = b0 + bl;
        if (b < HT_BINS)
            tile[bl][m] = g_acc[(size_t)b * BC + m];
    }
    __syncthreads();

    // store: thread handles (m, bl); consecutive t -> consecutive bl (coalesced)
    #pragma unroll
    for (int i = 0; i < 8; i++) {
        int idx = t + i * 256;          // idx = m*64 + bl
        int m  = idx >> 6;
        int bl = idx & 63;
        int b  = b0 + bl;
        if (b < HT_BINS)
            out[(size_t)m * HT_BINS + b] = tile[bl][m] * INV_NORM;
    }
}

// ---------------------------------------------------------------------------
// Launch: zero -> transpose -> votes -> finalize (all async, graph-capturable)
// ---------------------------------------------------------------------------
extern "C" void kernel_launch(void* const* d_in, const int* in_sizes, int n_in,
                              void* d_out, int out_size) {
    const float* x  = (const float*)d_in[0];   // [2,16,128,128] fp32
    const int*   vp = (const int*)  d_in[1];   // vote_pixel  [4M] int32
    const int*   vb = (const int*)  d_in[2];   // vote_bin    [4M] int32
    const float* vw = (const float*)d_in[3];   // vote_weight [4M] fp32
    float* out = (float*)d_out;                // [2,16,184,180] fp32

    const int TB = 256;

    zero_acc_kernel   <<<((HT_BINS * BC / 4) + TB - 1) / TB, TB>>>();
    transpose_x_kernel<<<IM_PIX / 64, TB>>>(x);

    long long work = (long long)N_VOTES * 8;
    int grid = (int)((work + TB - 1) / TB);
    vote_kernel<<<grid, TB>>>(vp, vb, vw);

    finalize_kernel<<<(HT_BINS + 63) / 64, TB>>>(out);
}